// round 1
// baseline (speedup 1.0000x reference)
#include <cuda_runtime.h>

// AUGRU (attention-modulated GRU), B=2048, T=200, D=H=64.
// Persistent per-CTA recurrence: each CTA owns M=14 batch rows and runs the
// full T loop locally. Weights live in REGISTERS (constant across steps/rows);
// per-row input vectors are broadcast-read from SMEM (warp-uniform addresses),
// making the kernel FFMA-pipe-bound rather than LDS-crossbar-bound.

#define B_ 2048
#define T_ 200
#define D_ 64
#define H_ 64
#define M_ 14
#define THREADS 512
#define NCTA ((B_ + M_ - 1) / M_)   // 147

__device__ __forceinline__ float sigmoid_f(float x) {
    return __fdividef(1.0f, 1.0f + __expf(-x));
}
__device__ __forceinline__ float tanh_f(float x) {
    float e = __expf(2.0f * x);
    return 1.0f - __fdividef(2.0f, e + 1.0f);
}

__global__ __launch_bounds__(THREADS, 1)
void augru_kernel(const float* __restrict__ x,      // [B,T,D]
                  const int*   __restrict__ slen_g, // [B]
                  const float* __restrict__ att,    // [B,T,1]
                  const float* __restrict__ gk,     // [128,128]
                  const float* __restrict__ gb,     // [128]
                  const float* __restrict__ ck,     // [128,64]
                  const float* __restrict__ cb,     // [64]
                  float*       __restrict__ out)    // [B,T,H]
{
    __shared__ __align__(16) float sx[M_][D_];   // x_t tile
    __shared__ __align__(16) float sh[M_][H_];   // hidden state
    __shared__ __align__(16) float srh[M_][H_];  // r * h
    __shared__ __align__(16) float su[M_][H_];   // update gate u
    __shared__ __align__(16) float psbuf[7 * M_ * 64]; // k-split partial sums
    __shared__ float sa[M_];
    __shared__ int   sl[M_];

    const int tid = threadIdx.x;
    const int b0  = blockIdx.x * M_;

    // Gate GEMM mapping: 128 output cols x 4-way k-split (32 k's each)
    const int gn  = tid & 127;
    const int gks = tid >> 7;
    // Cand GEMM mapping: 64 output cols x 8-way k-split (16 k's each)
    const int cn  = tid & 63;
    const int cks = tid >> 6;

    // Persistent register-resident weight slices
    float wg[32];
#pragma unroll
    for (int i = 0; i < 32; i++) wg[i] = gk[(gks * 32 + i) * 128 + gn];
    float wc[16];
#pragma unroll
    for (int i = 0; i < 16; i++) wc[i] = ck[(cks * 16 + i) * 64 + cn];
    const float gbias = gb[gn];
    const float cbias = cb[cn];

    // Init h = 0, load sequence lengths
    for (int idx = tid; idx < M_ * H_; idx += THREADS)
        (&sh[0][0])[idx] = 0.0f;
    if (tid < M_) {
        int b = b0 + tid; if (b >= B_) b = B_ - 1;
        sl[tid] = slen_g[b];
    }

    // Prefetch x(t=0), a(t=0) into registers
    const int pidx0 = tid;
    const int pidx1 = tid + THREADS;
    float xr0 = 0.f, xr1 = 0.f, ar = 0.f;
    {
        int m = pidx0 >> 6, k = pidx0 & 63;
        int b = b0 + m; if (b >= B_) b = B_ - 1;
        xr0 = x[(b * T_ + 0) * D_ + k];
        if (pidx1 < M_ * D_) {
            m = pidx1 >> 6; k = pidx1 & 63;
            b = b0 + m; if (b >= B_) b = B_ - 1;
            xr1 = x[(b * T_ + 0) * D_ + k];
        }
        if (tid < M_) {
            int bb = b0 + tid; if (bb >= B_) bb = B_ - 1;
            ar = att[bb * T_ + 0];
        }
    }
    __syncthreads();

    // Warp-uniform input base pointers for the two GEMMs
    const float* ginb = (gks < 2) ? (&sx[0][0] + gks * 32)
                                  : (&sh[0][0] + (gks - 2) * 32);
    const float* cinb = (cks < 4) ? (&sx[0][0] + cks * 16)
                                  : (&srh[0][0] + (cks - 4) * 16);

    for (int t = 0; t < T_; ++t) {
        // Commit prefetched x, a to SMEM (safe: prior iter's last sync done)
        (&sx[0][0])[pidx0] = xr0;
        if (pidx1 < M_ * D_) (&sx[0][0])[pidx1] = xr1;
        if (tid < M_) sa[tid] = ar;
        __syncthreads();

        // Prefetch next step's x, a (hidden under this step's compute)
        if (t + 1 < T_) {
            int m = pidx0 >> 6, k = pidx0 & 63;
            int b = b0 + m; if (b >= B_) b = B_ - 1;
            xr0 = x[(b * T_ + (t + 1)) * D_ + k];
            if (pidx1 < M_ * D_) {
                m = pidx1 >> 6; k = pidx1 & 63;
                b = b0 + m; if (b >= B_) b = B_ - 1;
                xr1 = x[(b * T_ + (t + 1)) * D_ + k];
            }
            if (tid < M_) {
                int bb = b0 + tid; if (bb >= B_) bb = B_ - 1;
                ar = att[bb * T_ + (t + 1)];
            }
        }

        // ---- Gate GEMM: pre = [x|h] @ Wg (partial over this thread's k-slice)
        float acc[M_];
#pragma unroll
        for (int m = 0; m < M_; m++) acc[m] = 0.f;
#pragma unroll
        for (int i = 0; i < 32; i += 4) {
#pragma unroll
            for (int m = 0; m < M_; m++) {
                float4 v = *reinterpret_cast<const float4*>(ginb + m * 64 + i);
                acc[m] = fmaf(wg[i    ], v.x, acc[m]);
                acc[m] = fmaf(wg[i + 1], v.y, acc[m]);
                acc[m] = fmaf(wg[i + 2], v.z, acc[m]);
                acc[m] = fmaf(wg[i + 3], v.w, acc[m]);
            }
        }
        if (gks != 0) {
#pragma unroll
            for (int m = 0; m < M_; m++)
                psbuf[((gks - 1) * M_ + m) * 128 + gn] = acc[m];
        }
        __syncthreads();

        // ---- Gate finalize: reduce k-split, sigmoid, produce r*h and u
        if (gks == 0) {
#pragma unroll
            for (int m = 0; m < M_; m++) {
                float g = acc[m]
                        + psbuf[(0 * M_ + m) * 128 + gn]
                        + psbuf[(1 * M_ + m) * 128 + gn]
                        + psbuf[(2 * M_ + m) * 128 + gn] + gbias;
                float s = sigmoid_f(g);
                if (gn < 64) srh[m][gn]      = s * sh[m][gn]; // r * h
                else         su[m][gn - 64]  = s;             // u
            }
        }
        __syncthreads();

        // ---- Candidate GEMM: cpre = [x|r*h] @ Wc (partial)
        float acc2[M_];
#pragma unroll
        for (int m = 0; m < M_; m++) acc2[m] = 0.f;
#pragma unroll
        for (int i = 0; i < 16; i += 4) {
#pragma unroll
            for (int m = 0; m < M_; m++) {
                float4 v = *reinterpret_cast<const float4*>(cinb + m * 64 + i);
                acc2[m] = fmaf(wc[i    ], v.x, acc2[m]);
                acc2[m] = fmaf(wc[i + 1], v.y, acc2[m]);
                acc2[m] = fmaf(wc[i + 2], v.z, acc2[m]);
                acc2[m] = fmaf(wc[i + 3], v.w, acc2[m]);
            }
        }
        if (cks != 0) {
#pragma unroll
            for (int m = 0; m < M_; m++)
                psbuf[((cks - 1) * M_ + m) * 64 + cn] = acc2[m];
        }
        __syncthreads();

        // ---- Candidate finalize + state update + output store
        if (cks == 0) {
#pragma unroll
            for (int m = 0; m < M_; m++) {
                float cp = acc2[m] + cbias;
#pragma unroll
                for (int j = 0; j < 7; j++)
                    cp += psbuf[(j * M_ + m) * 64 + cn];
                float c    = tanh_f(cp);
                float u    = su[m][cn];
                float uh   = (1.0f - sa[m]) * u;   // attention-modulated gate
                float hold = sh[m][cn];
                float hn   = uh * hold + (1.0f - uh) * c;
                bool valid = (t < sl[m]);
                sh[m][cn] = valid ? hn : hold;     // freeze past seq len
                int b = b0 + m;
                if (b < B_) out[(b * T_ + t) * H_ + cn] = valid ? hn : 0.0f;
            }
        }
        __syncthreads();
    }
}

extern "C" void kernel_launch(void* const* d_in, const int* in_sizes, int n_in,
                              void* d_out, int out_size) {
    const float* x   = (const float*)d_in[0]; // rnn_input [B,T,D]
    const int*   sl  = (const int*)  d_in[1]; // sequence_length [B]
    const float* att = (const float*)d_in[2]; // att_score [B,T,1]
    const float* gk  = (const float*)d_in[3]; // gate_kernel [128,128]
    const float* gb  = (const float*)d_in[4]; // gate_bias [128]
    const float* ck  = (const float*)d_in[5]; // cand_kernel [128,64]
    const float* cb  = (const float*)d_in[6]; // cand_bias [64]
    float* out = (float*)d_out;               // [B,T,H] fp32

    augru_kernel<<<NCTA, THREADS>>>(x, sl, att, gk, gb, ck, cb, out);
}

// round 2
// speedup vs baseline: 1.2042x; 1.2042x over previous
#include <cuda_runtime.h>

// AUGRU, B=2048, T=200, D=H=64. Persistent per-CTA recurrence, M=14 rows/CTA.
// Round-2 restructure: register n-tiling NT=4 (each thread owns 4 output
// columns; weight slice in regs) cuts broadcast-LDS delivered bytes 4x.
// K-split partials reduced through a shared ps[] buffer in a separate
// finalize phase. Double-buffered x/att commit folded into cand phase.

#define B_ 2048
#define T_ 200
#define D_ 64
#define H_ 64
#define M_ 14
#define THREADS 512
#define NCTA ((B_ + M_ - 1) / M_)   // 147

struct Smem {
    float sx[2][M_][64];   // x_t double buffer
    float sh[M_][64];      // hidden state
    float srh[M_][64];     // r * h
    float su[M_][64];      // update gate u
    float ps[14336];       // union: gate partials [8][14][128] / cand [16][14][64]
    float sa[2][M_];       // att double buffer
    int   sl[M_];
    float gb_s[128];
    float cb_s[64];
};
#define SMEM_BYTES ((int)sizeof(Smem))

__device__ __forceinline__ float sigmoid_f(float x) {
    return __fdividef(1.0f, 1.0f + __expf(-x));
}
__device__ __forceinline__ float tanh_f(float x) {
    float e = __expf(2.0f * x);
    return 1.0f - __fdividef(2.0f, e + 1.0f);
}

__global__ __launch_bounds__(THREADS, 1)
void augru_kernel(const float* __restrict__ x,      // [B,T,D]
                  const int*   __restrict__ slen_g, // [B]
                  const float* __restrict__ att,    // [B,T,1]
                  const float* __restrict__ gk,     // [128,128]
                  const float* __restrict__ gb,     // [128]
                  const float* __restrict__ ck,     // [128,64]
                  const float* __restrict__ cb,     // [64]
                  float*       __restrict__ out)    // [B,T,H]
{
    extern __shared__ char smem_raw[];
    Smem* S = reinterpret_cast<Smem*>(smem_raw);

    const int tid = threadIdx.x;
    const int b0  = blockIdx.x * M_;

    // Gate GEMM (K=128,N=128): 32 n-groups (NT=4) x KS=8 (kslice=16) x MG=2 (7 rows)
    const int gng = tid & 31;
    const int gks = (tid >> 5) & 7;
    const int gmh = tid >> 8;          // 0/1 -> rows gmh*7..gmh*7+6
    // Cand GEMM (K=128,N=64): 16 n-groups (NT=4) x KS=16 (kslice=8) x MG=2
    const int cng = tid & 15;
    const int cks = (tid >> 4) & 15;
    const int cmh = tid >> 8;

    // Persistent register weight tiles
    float wg[16][4];
#pragma unroll
    for (int i = 0; i < 16; i++)
#pragma unroll
        for (int c = 0; c < 4; c++)
            wg[i][c] = gk[(gks * 16 + i) * 128 + gng * 4 + c];
    float wc[8][4];
#pragma unroll
    for (int i = 0; i < 8; i++)
#pragma unroll
        for (int c = 0; c < 4; c++)
            wc[i][c] = ck[(cks * 8 + i) * 64 + cng * 4 + c];

    // One-time setup
    if (tid < 128) S->gb_s[tid] = gb[tid];
    if (tid < 64)  S->cb_s[tid] = cb[tid];
    for (int idx = tid; idx < M_ * 64; idx += THREADS)
        (&S->sh[0][0])[idx] = 0.0f;
    if (tid < M_) {
        int b = b0 + tid; if (b >= B_) b = B_ - 1;
        S->sl[tid] = slen_g[b];
    }

    // Prefetch + commit t=0
    float xr0, xr1 = 0.0f, ar = 0.0f;
    {
        int m = tid >> 6, k = tid & 63;
        int b = b0 + m; if (b >= B_) b = B_ - 1;
        xr0 = x[(b * T_) * D_ + k];
        if (tid < M_ * D_ - THREADS) {
            int p = tid + THREADS;
            m = p >> 6; k = p & 63;
            b = b0 + m; if (b >= B_) b = B_ - 1;
            xr1 = x[(b * T_) * D_ + k];
        }
        if (tid < M_) {
            int bb = b0 + tid; if (bb >= B_) bb = B_ - 1;
            ar = att[bb * T_];
        }
    }
    (&S->sx[0][0][0])[tid] = xr0;
    if (tid < M_ * D_ - THREADS) (&S->sx[0][0][0])[tid + THREADS] = xr1;
    if (tid < M_) S->sa[0][tid] = ar;
    __syncthreads();

    for (int t = 0; t < T_; ++t) {
        const int buf  = t & 1;
        const int nbuf = buf ^ 1;

        // Issue prefetch for t+1 (lands by phase C commit)
        {
            int tn = (t + 1 < T_) ? t + 1 : t;
            int m = tid >> 6, k = tid & 63;
            int b = b0 + m; if (b >= B_) b = B_ - 1;
            xr0 = x[(b * T_ + tn) * D_ + k];
            if (tid < M_ * D_ - THREADS) {
                int p = tid + THREADS;
                m = p >> 6; k = p & 63;
                b = b0 + m; if (b >= B_) b = B_ - 1;
                xr1 = x[(b * T_ + tn) * D_ + k];
            }
            if (tid < M_) {
                int bb = b0 + tid; if (bb >= B_) bb = B_ - 1;
                ar = att[bb * T_ + tn];
            }
        }

        // ---- Phase A: gate main (partial over k-slice), store partials
        {
            const float* gin = (gks < 4) ? (&S->sx[buf][0][0] + gks * 16)
                                         : (&S->sh[0][0]      + (gks - 4) * 16);
            float acc[7][4];
#pragma unroll
            for (int mm = 0; mm < 7; mm++)
#pragma unroll
                for (int c = 0; c < 4; c++) acc[mm][c] = 0.0f;

#pragma unroll
            for (int mm = 0; mm < 7; mm++) {
                const float* p = gin + (gmh * 7 + mm) * 64;
#pragma unroll
                for (int i = 0; i < 16; i += 4) {
                    float4 v = *reinterpret_cast<const float4*>(p + i);
#pragma unroll
                    for (int c = 0; c < 4; c++) {
                        acc[mm][c] = fmaf(wg[i    ][c], v.x, acc[mm][c]);
                        acc[mm][c] = fmaf(wg[i + 1][c], v.y, acc[mm][c]);
                        acc[mm][c] = fmaf(wg[i + 2][c], v.z, acc[mm][c]);
                        acc[mm][c] = fmaf(wg[i + 3][c], v.w, acc[mm][c]);
                    }
                }
            }
#pragma unroll
            for (int mm = 0; mm < 7; mm++) {
                int m = gmh * 7 + mm;
                *reinterpret_cast<float4*>(&S->ps[(gks * M_ + m) * 128 + gng * 4]) =
                    make_float4(acc[mm][0], acc[mm][1], acc[mm][2], acc[mm][3]);
            }
        }
        __syncthreads();

        // ---- Phase B: gate finalize (reduce 8 partials, sigmoid, srh/su)
#pragma unroll
        for (int i = 0; i < 4; i++) {
            int o = tid + (i << 9);
            if (o < M_ * 128) {
                int n = o & 127, m = o >> 7;
                float s = S->gb_s[n];
#pragma unroll
                for (int ks = 0; ks < 8; ks++)
                    s += S->ps[(ks * M_ + m) * 128 + n];
                float sig = sigmoid_f(s);
                if (n < 64) S->srh[m][n]      = sig * S->sh[m][n];
                else        S->su[m][n - 64]  = sig;
            }
        }
        __syncthreads();

        // ---- Phase C: cand main + store partials + commit prefetched x/a
        {
            const float* cin = (cks < 8) ? (&S->sx[buf][0][0] + cks * 8)
                                         : (&S->srh[0][0]     + (cks - 8) * 8);
            float acc[7][4];
#pragma unroll
            for (int mm = 0; mm < 7; mm++)
#pragma unroll
                for (int c = 0; c < 4; c++) acc[mm][c] = 0.0f;

#pragma unroll
            for (int mm = 0; mm < 7; mm++) {
                const float* p = cin + (cmh * 7 + mm) * 64;
#pragma unroll
                for (int i = 0; i < 8; i += 4) {
                    float4 v = *reinterpret_cast<const float4*>(p + i);
#pragma unroll
                    for (int c = 0; c < 4; c++) {
                        acc[mm][c] = fmaf(wc[i    ][c], v.x, acc[mm][c]);
                        acc[mm][c] = fmaf(wc[i + 1][c], v.y, acc[mm][c]);
                        acc[mm][c] = fmaf(wc[i + 2][c], v.z, acc[mm][c]);
                        acc[mm][c] = fmaf(wc[i + 3][c], v.w, acc[mm][c]);
                    }
                }
            }
#pragma unroll
            for (int mm = 0; mm < 7; mm++) {
                int m = cmh * 7 + mm;
                *reinterpret_cast<float4*>(&S->ps[(cks * M_ + m) * 64 + cng * 4]) =
                    make_float4(acc[mm][0], acc[mm][1], acc[mm][2], acc[mm][3]);
            }
            // commit prefetched t+1 inputs into the other buffer
            (&S->sx[nbuf][0][0])[tid] = xr0;
            if (tid < M_ * D_ - THREADS) (&S->sx[nbuf][0][0])[tid + THREADS] = xr1;
            if (tid < M_) S->sa[nbuf][tid] = ar;
        }
        __syncthreads();

        // ---- Phase D: cand finalize (reduce 16 partials, tanh, h update, out)
#pragma unroll
        for (int i = 0; i < 2; i++) {
            int o = tid + (i << 9);
            if (o < M_ * 64) {
                int n = o & 63, m = o >> 6;
                float s = S->cb_s[n];
#pragma unroll
                for (int ks = 0; ks < 16; ks++)
                    s += S->ps[(ks * M_ + m) * 64 + n];
                float c    = tanh_f(s);
                float u    = S->su[m][n];
                float a    = S->sa[buf][m];
                float uh   = (1.0f - a) * u;
                float hold = S->sh[m][n];
                float hn   = uh * hold + (1.0f - uh) * c;
                bool valid = (t < S->sl[m]);
                S->sh[m][n] = valid ? hn : hold;
                int b = b0 + m;
                if (b < B_) out[(b * T_ + t) * H_ + n] = valid ? hn : 0.0f;
            }
        }
        __syncthreads();
    }
}

extern "C" void kernel_launch(void* const* d_in, const int* in_sizes, int n_in,
                              void* d_out, int out_size) {
    const float* x   = (const float*)d_in[0];
    const int*   sl  = (const int*)  d_in[1];
    const float* att = (const float*)d_in[2];
    const float* gk  = (const float*)d_in[3];
    const float* gb  = (const float*)d_in[4];
    const float* ck  = (const float*)d_in[5];
    const float* cb  = (const float*)d_in[6];
    float* out = (float*)d_out;

    cudaFuncSetAttribute(augru_kernel,
                         cudaFuncAttributeMaxDynamicSharedMemorySize, SMEM_BYTES);
    augru_kernel<<<NCTA, THREADS, SMEM_BYTES>>>(x, sl, att, gk, gb, ck, cb, out);
}

// round 3
// speedup vs baseline: 1.2971x; 1.0772x over previous
#include <cuda_runtime.h>

// AUGRU, B=2048, T=200, D=H=64.
// Two-kernel split:
//  K1: precompute Y1 = x@Wgx + gb  [B*T,128],  Y2 = x@Wcx + cb [B*T,64]
//      (the non-recurrent half of the FLOPs, parallel GEMM).
//  K2: persistent recurrence with K=64 (h-part only), 2 CTAs/SM, M=7 rows/CTA.

#define B_ 2048
#define T_ 200
#define D_ 64
#define H_ 64

// ---------------- scratch (no-alloc rule: __device__ globals) ----------------
__device__ float Y1g[B_ * T_ * 128];
__device__ float Y2g[B_ * T_ * 64];

__device__ __forceinline__ float sigmoid_f(float x) {
    return __fdividef(1.0f, 1.0f + __expf(-x));
}
__device__ __forceinline__ float tanh_f(float x) {
    float e = __expf(2.0f * x);
    return 1.0f - __fdividef(2.0f, e + 1.0f);
}

// ============================ K1: precompute ================================
// [BT,64] @ [64,192] -> Y1|Y2. 384 threads: 96 col-groups (NT=2) x 4 rows.
// Weights (64x2 slice) register-resident per thread; x rows broadcast from smem.
#define PRE_THREADS 384
#define PRE_GRID 1480
#define TILE_R 8

__global__ __launch_bounds__(PRE_THREADS, 1)
void pre_kernel(const float* __restrict__ x,   // [B*T, 64]
                const float* __restrict__ gk,  // [128,128]
                const float* __restrict__ gb,
                const float* __restrict__ ck,  // [128,64]
                const float* __restrict__ cb)
{
    __shared__ float sx[TILE_R][64];
    const int tid  = threadIdx.x;
    const int g    = tid % 96;     // cols 2g, 2g+1 of [Y1(128) | Y2(64)]
    const int rsub = tid / 96;     // 0..3

    float w[64][2];
    float b0v, b1v;
    if (g < 64) {
#pragma unroll
        for (int k = 0; k < 64; k++) {
            w[k][0] = gk[k * 128 + 2 * g];
            w[k][1] = gk[k * 128 + 2 * g + 1];
        }
        b0v = gb[2 * g]; b1v = gb[2 * g + 1];
    } else {
        int c = 2 * (g - 64);
#pragma unroll
        for (int k = 0; k < 64; k++) {
            w[k][0] = ck[k * 64 + c];
            w[k][1] = ck[k * 64 + c + 1];
        }
        b0v = cb[c]; b1v = cb[c + 1];
    }

    const int ntiles = (B_ * T_) / TILE_R;   // 51200
    int tile = blockIdx.x;
    float4 pf = make_float4(0.f, 0.f, 0.f, 0.f);
    if (tile < ntiles && tid < 128)
        pf = ((const float4*)(x + (size_t)tile * TILE_R * 64))[tid];

    for (; tile < ntiles; tile += PRE_GRID) {
        __syncthreads();                      // sx free from previous tile
        if (tid < 128) ((float4*)&sx[0][0])[tid] = pf;
        __syncthreads();
        int nt = tile + PRE_GRID;
        if (nt < ntiles && tid < 128)
            pf = ((const float4*)(x + (size_t)nt * TILE_R * 64))[tid];

#pragma unroll
        for (int pass = 0; pass < 2; pass++) {
            const int r = pass * 4 + rsub;
            const float* xr = sx[r];
            float a0 = b0v, a1 = b1v;
#pragma unroll
            for (int k = 0; k < 64; k += 4) {
                float4 v = *reinterpret_cast<const float4*>(xr + k);
                a0 = fmaf(w[k    ][0], v.x, a0);
                a0 = fmaf(w[k + 1][0], v.y, a0);
                a0 = fmaf(w[k + 2][0], v.z, a0);
                a0 = fmaf(w[k + 3][0], v.w, a0);
                a1 = fmaf(w[k    ][1], v.x, a1);
                a1 = fmaf(w[k + 1][1], v.y, a1);
                a1 = fmaf(w[k + 2][1], v.z, a1);
                a1 = fmaf(w[k + 3][1], v.w, a1);
            }
            int rowg = tile * TILE_R + r;
            if (g < 64)
                *reinterpret_cast<float2*>(&Y1g[rowg * 128 + 2 * g]) = make_float2(a0, a1);
            else
                *reinterpret_cast<float2*>(&Y2g[rowg * 64 + 2 * (g - 64)]) = make_float2(a0, a1);
        }
    }
}

// ============================ K2: recurrence ================================
#define M_ 7
#define RTHREADS 256
#define NCTA_R ((B_ + M_ - 1) / M_)   // 293

struct RSmem {
    float sy1[2][M_][128];
    float sy2[2][M_][64];
    float sh[M_][64];
    float srh[M_][64];
    float su[M_][64];
    float ps[8 * M_ * 128];   // gate partials [8][7][128]; cand reuses [16][7][64]
    float sa[2][8];
    int   sl[8];
};
#define RSMEM_BYTES ((int)sizeof(RSmem))

__global__ __launch_bounds__(RTHREADS, 2)
void augru_rec_kernel(const int*   __restrict__ slen_g,
                      const float* __restrict__ gk,   // [128,128] (h rows 64..127)
                      const float* __restrict__ ck,   // [128,64]
                      float*       __restrict__ out)  // [B,T,64]
{
    extern __shared__ char smem_raw[];
    RSmem* S = reinterpret_cast<RSmem*>(smem_raw);

    const int tid = threadIdx.x;
    const int b0  = blockIdx.x * M_;

    // gate: N=128, K=64(h). 32 n-groups (NT=4) x 8 k-slices (8 k each)
    const int gng = tid & 31;
    const int gks = tid >> 5;
    // cand: N=64, K=64(rh). 16 n-groups x 16 k-slices (4 k each)
    const int cng = tid & 15;
    const int cks = tid >> 4;

    float wg[8][4];
#pragma unroll
    for (int i = 0; i < 8; i++)
#pragma unroll
        for (int c = 0; c < 4; c++)
            wg[i][c] = gk[(64 + gks * 8 + i) * 128 + gng * 4 + c];
    float wc[4][4];
#pragma unroll
    for (int i = 0; i < 4; i++)
#pragma unroll
        for (int c = 0; c < 4; c++)
            wc[i][c] = ck[(64 + cks * 4 + i) * 64 + cng * 4 + c];

    // init
    for (int idx = tid; idx < M_ * 64; idx += RTHREADS)
        (&S->sh[0][0])[idx] = 0.0f;
    if (tid < M_) {
        int b = b0 + tid; if (b >= B_) b = B_ - 1;
        S->sl[tid] = slen_g[b];
    }

    // prefetch lane roles
    const int y1m = tid >> 5, y1q = tid & 31;      // tid<224: sy1 float4
    const int y2m = tid >> 4, y2q = tid & 15;      // tid<112: sy2 float4
    float4 py1 = make_float4(0,0,0,0), py2 = make_float4(0,0,0,0);
    float pa = 0.0f;

    // t=0 prefetch + commit
    {
        if (tid < 224) {
            int b = b0 + y1m; if (b >= B_) b = B_ - 1;
            py1 = *reinterpret_cast<const float4*>(&Y1g[(b * T_) * 128 + y1q * 4]);
        }
        if (tid < 112) {
            int b = b0 + y2m; if (b >= B_) b = B_ - 1;
            py2 = *reinterpret_cast<const float4*>(&Y2g[(b * T_) * 64 + y2q * 4]);
        }
        if (tid < M_) {
            int b = b0 + tid; if (b >= B_) b = B_ - 1;
            pa = __ldg(&((const float*)nullptr == nullptr ?  // keep simple
                         (const float*)0 : (const float*)0)[0]); // placeholder removed below
        }
    }
    // (att pointer passed separately — see launch; re-read here properly)
    // NOTE: att handled via attg pointer param below.
    (void)pa;

    // --- real t=0 commit happens in-loop via a "first iteration" pattern:
    if (tid < 224) *reinterpret_cast<float4*>(&S->sy1[0][0][0] + tid * 4) = py1;
    if (tid < 112) *reinterpret_cast<float4*>(&S->sy2[0][0][0] + tid * 4) = py2;
    __syncthreads();

    // (the kernel body continues in augru_rec_kernel2 — unreachable; see below)
}

// The version above had an att-plumbing mistake; the actual kernel used is this:
__global__ __launch_bounds__(RTHREADS, 2)
void augru_rec(const int*   __restrict__ slen_g,
               const float* __restrict__ att,   // [B,T]
               const float* __restrict__ gk,
               const float* __restrict__ ck,
               float*       __restrict__ out)
{
    extern __shared__ char smem_raw[];
    RSmem* S = reinterpret_cast<RSmem*>(smem_raw);

    const int tid = threadIdx.x;
    const int b0  = blockIdx.x * M_;

    const int gng = tid & 31;
    const int gks = tid >> 5;
    const int cng = tid & 15;
    const int cks = tid >> 4;

    float wg[8][4];
#pragma unroll
    for (int i = 0; i < 8; i++)
#pragma unroll
        for (int c = 0; c < 4; c++)
            wg[i][c] = gk[(64 + gks * 8 + i) * 128 + gng * 4 + c];
    float wc[4][4];
#pragma unroll
    for (int i = 0; i < 4; i++)
#pragma unroll
        for (int c = 0; c < 4; c++)
            wc[i][c] = ck[(64 + cks * 4 + i) * 64 + cng * 4 + c];

    for (int idx = tid; idx < M_ * 64; idx += RTHREADS)
        (&S->sh[0][0])[idx] = 0.0f;
    if (tid < M_) {
        int b = b0 + tid; if (b >= B_) b = B_ - 1;
        S->sl[tid] = slen_g[b];
    }

    const int y1m = tid >> 5, y1q = tid & 31;
    const int y2m = tid >> 4, y2q = tid & 15;
    int by1 = b0 + y1m; if (by1 >= B_) by1 = B_ - 1;
    int by2 = b0 + y2m; if (by2 >= B_) by2 = B_ - 1;
    int ba  = b0 + tid; if (ba  >= B_) ba  = B_ - 1;

    float4 py1 = make_float4(0,0,0,0), py2 = make_float4(0,0,0,0);
    float pa = 0.0f;
    if (tid < 224) py1 = *reinterpret_cast<const float4*>(&Y1g[(by1 * T_) * 128 + y1q * 4]);
    if (tid < 112) py2 = *reinterpret_cast<const float4*>(&Y2g[(by2 * T_) * 64 + y2q * 4]);
    if (tid < M_)  pa  = att[ba * T_];

    // commit t=0
    if (tid < 224) reinterpret_cast<float4*>(&S->sy1[0][0][0])[tid] = py1;
    if (tid < 112) reinterpret_cast<float4*>(&S->sy2[0][0][0])[tid] = py2;
    if (tid < M_)  S->sa[0][tid] = pa;
    __syncthreads();

    for (int t = 0; t < T_; ++t) {
        const int buf  = t & 1;
        const int nbuf = buf ^ 1;

        // issue prefetch for t+1
        {
            int tn = (t + 1 < T_) ? t + 1 : t;
            if (tid < 224) py1 = *reinterpret_cast<const float4*>(&Y1g[(by1 * T_ + tn) * 128 + y1q * 4]);
            if (tid < 112) py2 = *reinterpret_cast<const float4*>(&Y2g[(by2 * T_ + tn) * 64 + y2q * 4]);
            if (tid < M_)  pa  = att[ba * T_ + tn];
        }

        // ---- Phase A: gate h-GEMM partials  (reads sh)
        {
            const float* gin = &S->sh[0][0] + gks * 8;
            float acc[M_][4];
#pragma unroll
            for (int m = 0; m < M_; m++)
#pragma unroll
                for (int c = 0; c < 4; c++) acc[m][c] = 0.0f;
#pragma unroll
            for (int m = 0; m < M_; m++) {
                const float* p = gin + m * 64;
                float4 v0 = *reinterpret_cast<const float4*>(p);
                float4 v1 = *reinterpret_cast<const float4*>(p + 4);
#pragma unroll
                for (int c = 0; c < 4; c++) {
                    acc[m][c] = fmaf(wg[0][c], v0.x, acc[m][c]);
                    acc[m][c] = fmaf(wg[1][c], v0.y, acc[m][c]);
                    acc[m][c] = fmaf(wg[2][c], v0.z, acc[m][c]);
                    acc[m][c] = fmaf(wg[3][c], v0.w, acc[m][c]);
                    acc[m][c] = fmaf(wg[4][c], v1.x, acc[m][c]);
                    acc[m][c] = fmaf(wg[5][c], v1.y, acc[m][c]);
                    acc[m][c] = fmaf(wg[6][c], v1.z, acc[m][c]);
                    acc[m][c] = fmaf(wg[7][c], v1.w, acc[m][c]);
                }
            }
#pragma unroll
            for (int m = 0; m < M_; m++)
                *reinterpret_cast<float4*>(&S->ps[(gks * M_ + m) * 128 + gng * 4]) =
                    make_float4(acc[m][0], acc[m][1], acc[m][2], acc[m][3]);
        }
        __syncthreads();

        // ---- Phase B: gate finalize (Y1 + partials, sigmoid -> srh/su)
#pragma unroll
        for (int i = 0; i < 4; i++) {
            int o = tid + (i << 8);
            if (o < M_ * 128) {
                int n = o & 127, m = o >> 7;
                float s = S->sy1[buf][m][n];
#pragma unroll
                for (int ks = 0; ks < 8; ks++)
                    s += S->ps[(ks * M_ + m) * 128 + n];
                float sig = sigmoid_f(s);
                if (n < 64) S->srh[m][n]     = sig * S->sh[m][n];
                else        S->su[m][n - 64] = sig;
            }
        }
        __syncthreads();

        // ---- Phase C: cand rh-GEMM partials + commit prefetched Y/att
        {
            const float* cin = &S->srh[0][0] + cks * 4;
            float acc[M_][4];
#pragma unroll
            for (int m = 0; m < M_; m++)
#pragma unroll
                for (int c = 0; c < 4; c++) acc[m][c] = 0.0f;
#pragma unroll
            for (int m = 0; m < M_; m++) {
                float4 v = *reinterpret_cast<const float4*>(cin + m * 64);
#pragma unroll
                for (int c = 0; c < 4; c++) {
                    acc[m][c] = fmaf(wc[0][c], v.x, acc[m][c]);
                    acc[m][c] = fmaf(wc[1][c], v.y, acc[m][c]);
                    acc[m][c] = fmaf(wc[2][c], v.z, acc[m][c]);
                    acc[m][c] = fmaf(wc[3][c], v.w, acc[m][c]);
                }
            }
#pragma unroll
            for (int m = 0; m < M_; m++)
                *reinterpret_cast<float4*>(&S->ps[(cks * M_ + m) * 64 + cng * 4]) =
                    make_float4(acc[m][0], acc[m][1], acc[m][2], acc[m][3]);

            if (tid < 224) reinterpret_cast<float4*>(&S->sy1[nbuf][0][0])[tid] = py1;
            if (tid < 112) reinterpret_cast<float4*>(&S->sy2[nbuf][0][0])[tid] = py2;
            if (tid < M_)  S->sa[nbuf][tid] = pa;
        }
        __syncthreads();

        // ---- Phase D: cand finalize + h update + output
#pragma unroll
        for (int i = 0; i < 2; i++) {
            int o = tid + (i << 8);
            if (o < M_ * 64) {
                int n = o & 63, m = o >> 6;
                float s = S->sy2[buf][m][n];
#pragma unroll
                for (int ks = 0; ks < 16; ks++)
                    s += S->ps[(ks * M_ + m) * 64 + n];
                float c    = tanh_f(s);
                float u    = S->su[m][n];
                float a    = S->sa[buf][m];
                float uh   = (1.0f - a) * u;
                float hold = S->sh[m][n];
                float hn   = uh * hold + (1.0f - uh) * c;
                bool valid = (t < S->sl[m]);
                S->sh[m][n] = valid ? hn : hold;
                int b = b0 + m;
                if (b < B_) out[(b * T_ + t) * 64 + n] = valid ? hn : 0.0f;
            }
        }
        __syncthreads();
    }
}

extern "C" void kernel_launch(void* const* d_in, const int* in_sizes, int n_in,
                              void* d_out, int out_size) {
    const float* x   = (const float*)d_in[0];
    const int*   sl  = (const int*)  d_in[1];
    const float* att = (const float*)d_in[2];
    const float* gk  = (const float*)d_in[3];
    const float* gb  = (const float*)d_in[4];
    const float* ck  = (const float*)d_in[5];
    const float* cb  = (const float*)d_in[6];
    float* out = (float*)d_out;

    pre_kernel<<<PRE_GRID, PRE_THREADS>>>(x, gk, gb, ck, cb);

    cudaFuncSetAttribute(augru_rec,
                         cudaFuncAttributeMaxDynamicSharedMemorySize, RSMEM_BYTES);
    augru_rec<<<NCTA_R, RTHREADS, RSMEM_BYTES>>>(sl, att, gk, ck, out);
}

// round 4
// speedup vs baseline: 1.3588x; 1.0476x over previous
#include <cuda_runtime.h>
#include <cstdint>

// AUGRU, B=2048, T=200, D=H=64. Two-kernel split + packed f32x2 math.
//  K1 (pre): Y1 = x@Wgx + gb [BT,128], Y2 = x@Wcx + cb [BT,64]
//  K2 (rec): persistent recurrence, K=64 h-part, 2 CTAs/SM, M=7 rows/CTA.

#define B_ 2048
#define T_ 200
#define D_ 64
#define H_ 64

typedef unsigned long long ull;

__device__ float Y1g[B_ * T_ * 128];
__device__ float Y2g[B_ * T_ * 64];

__device__ __forceinline__ ull pack2(float lo, float hi) {
    ull r; asm("mov.b64 %0, {%1, %2};" : "=l"(r) : "f"(lo), "f"(hi)); return r;
}
__device__ __forceinline__ void unpack2(ull v, float& lo, float& hi) {
    asm("mov.b64 {%0, %1}, %2;" : "=f"(lo), "=f"(hi) : "l"(v));
}
__device__ __forceinline__ ull ffma2(ull a, ull b, ull c) {
    ull d; asm("fma.rn.f32x2 %0, %1, %2, %3;" : "=l"(d) : "l"(a), "l"(b), "l"(c)); return d;
}
__device__ __forceinline__ ull add2(ull a, ull b) {
    ull d; asm("add.rn.f32x2 %0, %1, %2;" : "=l"(d) : "l"(a), "l"(b)); return d;
}
__device__ __forceinline__ float hadd2(ull v) {
    float lo, hi; unpack2(v, lo, hi); return lo + hi;
}
__device__ __forceinline__ float sigmoid_f(float x) {
    return __fdividef(1.0f, 1.0f + __expf(-x));
}
__device__ __forceinline__ float tanh_f(float x) {
    float e = __expf(2.0f * x);
    return 1.0f - __fdividef(2.0f, e + 1.0f);
}
__device__ __forceinline__ void cpa16(void* s, const void* g) {
    uint32_t sa = (uint32_t)__cvta_generic_to_shared(s);
    asm volatile("cp.async.ca.shared.global [%0], [%1], 16;" :: "r"(sa), "l"(g));
}
__device__ __forceinline__ void cpa4(void* s, const void* g) {
    uint32_t sa = (uint32_t)__cvta_generic_to_shared(s);
    asm volatile("cp.async.ca.shared.global [%0], [%1], 4;" :: "r"(sa), "l"(g));
}

// ============================ K1: precompute ================================
// [BT,64] @ [64,192]. 384 threads: 48 col-groups (NT=4) x 2 k-slices x 4 row-subs.
// FFMA2 with natural k-pair packing; 1-round shfl reduce across the k-split.
#define PRE_THREADS 384
#define PRE_GRID 1480
#define TILE_R 8

__global__ __launch_bounds__(PRE_THREADS, 1)
void pre_kernel(const float* __restrict__ x,   // [B*T, 64]
                const float* __restrict__ gk,  // [128,128]
                const float* __restrict__ gb,
                const float* __restrict__ ck,  // [128,64]
                const float* __restrict__ cb)
{
    __shared__ __align__(16) float sx[TILE_R][64];
    const int tid  = threadIdx.x;
    const int ks   = tid & 1;          // k-half (32 k each)
    const int cg   = (tid >> 1) % 48;  // 4 cols
    const int rsub = tid / 96;         // rows {rsub, rsub+4}
    const int col0 = cg * 4;

    // Pre-packed weight k-pairs: w2[kp][c] = (W[k0][col], W[k0+1][col])
    ull w2[16][4];
#pragma unroll
    for (int kp = 0; kp < 16; kp++) {
        int k = ks * 32 + 2 * kp;
#pragma unroll
        for (int c = 0; c < 4; c++) {
            int col = col0 + c;
            float a, b;
            if (col < 128) { a = gk[k * 128 + col];       b = gk[(k + 1) * 128 + col]; }
            else           { a = ck[k * 64 + col - 128];  b = ck[(k + 1) * 64 + col - 128]; }
            w2[kp][c] = pack2(a, b);
        }
    }
    float bias[4];
#pragma unroll
    for (int c = 0; c < 4; c++) {
        int col = col0 + c;
        bias[c] = (col < 128) ? gb[col] : cb[col - 128];
    }

    const int ntiles = (B_ * T_) / TILE_R;   // 51200
    int tile = blockIdx.x;
    float4 pf = make_float4(0.f, 0.f, 0.f, 0.f);
    if (tile < ntiles && tid < 128)
        pf = ((const float4*)(x + (size_t)tile * TILE_R * 64))[tid];

    for (; tile < ntiles; tile += PRE_GRID) {
        __syncthreads();
        if (tid < 128) ((float4*)&sx[0][0])[tid] = pf;
        __syncthreads();
        int nt = tile + PRE_GRID;
        if (nt < ntiles && tid < 128)
            pf = ((const float4*)(x + (size_t)nt * TILE_R * 64))[tid];

#pragma unroll
        for (int pass = 0; pass < 2; pass++) {
            const int r = rsub + pass * 4;
            ull acc[4] = {0ull, 0ull, 0ull, 0ull};
            const ulonglong2* xr = (const ulonglong2*)&sx[r][ks * 32];
#pragma unroll
            for (int q = 0; q < 8; q++) {
                ulonglong2 v = xr[q];
#pragma unroll
                for (int c = 0; c < 4; c++) {
                    acc[c] = ffma2(w2[2 * q][c],     v.x, acc[c]);
                    acc[c] = ffma2(w2[2 * q + 1][c], v.y, acc[c]);
                }
            }
#pragma unroll
            for (int c = 0; c < 4; c++)
                acc[c] = add2(acc[c], __shfl_xor_sync(0xffffffffu, acc[c], 1));
            if (ks == 0) {
                float4 s;
                s.x = hadd2(acc[0]) + bias[0];
                s.y = hadd2(acc[1]) + bias[1];
                s.z = hadd2(acc[2]) + bias[2];
                s.w = hadd2(acc[3]) + bias[3];
                int rowg = tile * TILE_R + r;
                if (col0 < 128)
                    *reinterpret_cast<float4*>(&Y1g[rowg * 128 + col0]) = s;
                else
                    *reinterpret_cast<float4*>(&Y2g[rowg * 64 + col0 - 128]) = s;
            }
        }
    }
}

// ============================ K2: recurrence ================================
#define M_ 7
#define RTHREADS 256
#define NCTA_R ((B_ + M_ - 1) / M_)   // 293

struct RSmem {
    float sy1[2][M_][128];
    float sy2[2][M_][64];
    float sh[M_][64];
    float srh[M_][64];
    float su[M_][64];
    float ps[8 * M_ * 128];   // gate [8][7][128]; cand reuses as [16][7][64]
    float sa[2][8];
    int   sl[8];
};
#define RSMEM_BYTES ((int)sizeof(RSmem))

__global__ __launch_bounds__(RTHREADS, 2)
void augru_rec(const int*   __restrict__ slen_g,
               const float* __restrict__ att,   // [B,T]
               const float* __restrict__ gk,
               const float* __restrict__ ck,
               float*       __restrict__ out)
{
    extern __shared__ char smem_raw[];
    RSmem* S = reinterpret_cast<RSmem*>(smem_raw);

    const int tid = threadIdx.x;
    const int b0  = blockIdx.x * M_;

    // gate: N=128, K=64(h): 32 n-groups (NT=4) x 8 k-slices (8 k = 4 k-pairs)
    const int gng = tid & 31;
    const int gks = tid >> 5;
    // cand: N=64, K=64(rh): 16 n-groups x 16 k-slices (4 k = 2 k-pairs)
    const int cng = tid & 15;
    const int cks = tid >> 4;

    ull wg2[4][4];
#pragma unroll
    for (int kp = 0; kp < 4; kp++)
#pragma unroll
        for (int c = 0; c < 4; c++)
            wg2[kp][c] = pack2(gk[(64 + gks * 8 + 2 * kp)     * 128 + gng * 4 + c],
                               gk[(64 + gks * 8 + 2 * kp + 1) * 128 + gng * 4 + c]);
    ull wc2[2][4];
#pragma unroll
    for (int kp = 0; kp < 2; kp++)
#pragma unroll
        for (int c = 0; c < 4; c++)
            wc2[kp][c] = pack2(ck[(64 + cks * 4 + 2 * kp)     * 64 + cng * 4 + c],
                               ck[(64 + cks * 4 + 2 * kp + 1) * 64 + cng * 4 + c]);

    for (int idx = tid; idx < M_ * 64; idx += RTHREADS)
        (&S->sh[0][0])[idx] = 0.0f;
    if (tid < M_) {
        int b = b0 + tid; if (b >= B_) b = B_ - 1;
        S->sl[tid] = slen_g[b];
    }

    const int y1m = tid >> 5, y1q = tid & 31;
    const int y2m = tid >> 4, y2q = tid & 15;
    int by1 = b0 + y1m; if (by1 >= B_) by1 = B_ - 1;
    int by2 = b0 + y2m; if (by2 >= B_) by2 = B_ - 1;
    int ba  = b0 + tid; if (ba  >= B_) ba  = B_ - 1;

    // prefetch (cp.async) time tt into buffer bb
    auto do_prefetch = [&](int tt, int bb) {
        if (tid < 224)
            cpa16((char*)&S->sy1[bb][0][0] + tid * 16,
                  &Y1g[(by1 * T_ + tt) * 128 + y1q * 4]);
        if (tid < 112)
            cpa16((char*)&S->sy2[bb][0][0] + tid * 16,
                  &Y2g[(by2 * T_ + tt) * 64 + y2q * 4]);
        if (tid < M_)
            cpa4(&S->sa[bb][tid], &att[ba * T_ + tt]);
        asm volatile("cp.async.commit_group;");
    };

    do_prefetch(0, 0);
    asm volatile("cp.async.wait_group 0;");
    __syncthreads();

    for (int t = 0; t < T_; ++t) {
        const int buf  = t & 1;
        const int nbuf = buf ^ 1;
        do_prefetch((t + 1 < T_) ? t + 1 : t, nbuf);

        // ---- Phase A: gate h-GEMM partials (FFMA2, k-pair packed)
#pragma unroll
        for (int mh = 0; mh < 2; mh++) {
            const int mbase = mh * 4;
            const int mcnt  = mh ? 3 : 4;
            ull acc[4][4];
#pragma unroll
            for (int mm = 0; mm < 4; mm++)
#pragma unroll
                for (int c = 0; c < 4; c++) acc[mm][c] = 0ull;
#pragma unroll
            for (int mm = 0; mm < 4; mm++) {
                if (mm >= mcnt) break;
                const ulonglong2* p = (const ulonglong2*)&S->sh[mbase + mm][gks * 8];
                ulonglong2 v0 = p[0], v1 = p[1];
#pragma unroll
                for (int c = 0; c < 4; c++) {
                    acc[mm][c] = ffma2(wg2[0][c], v0.x, acc[mm][c]);
                    acc[mm][c] = ffma2(wg2[1][c], v0.y, acc[mm][c]);
                    acc[mm][c] = ffma2(wg2[2][c], v1.x, acc[mm][c]);
                    acc[mm][c] = ffma2(wg2[3][c], v1.y, acc[mm][c]);
                }
            }
#pragma unroll
            for (int mm = 0; mm < 4; mm++) {
                if (mm >= mcnt) break;
                float4 s;
                s.x = hadd2(acc[mm][0]); s.y = hadd2(acc[mm][1]);
                s.z = hadd2(acc[mm][2]); s.w = hadd2(acc[mm][3]);
                *reinterpret_cast<float4*>(
                    &S->ps[(gks * M_ + mbase + mm) * 128 + gng * 4]) = s;
            }
        }
        __syncthreads();

        // ---- Phase B: gate finalize (packed adds, sigmoid -> srh/su)
#pragma unroll
        for (int it = 0; it < 2; it++) {
            int p = tid + it * 256;
            if (p < M_ * 64) {
                int m = p >> 6, n0 = (p & 63) * 2;
                ull s = *(const ull*)&S->sy1[buf][m][n0];
#pragma unroll
                for (int k2 = 0; k2 < 8; k2++)
                    s = add2(s, *(const ull*)&S->ps[(k2 * M_ + m) * 128 + n0]);
                float g0, g1; unpack2(s, g0, g1);
                g0 = sigmoid_f(g0); g1 = sigmoid_f(g1);
                if (n0 < 64) {
                    float2 hv = *(const float2*)&S->sh[m][n0];
                    float2 o; o.x = g0 * hv.x; o.y = g1 * hv.y;
                    *(float2*)&S->srh[m][n0] = o;
                } else {
                    float2 o; o.x = g0; o.y = g1;
                    *(float2*)&S->su[m][n0 - 64] = o;
                }
            }
        }
        __syncthreads();

        // ---- Phase C: cand rh-GEMM partials
#pragma unroll
        for (int mh = 0; mh < 2; mh++) {
            const int mbase = mh * 4;
            const int mcnt  = mh ? 3 : 4;
            ull acc[4][4];
#pragma unroll
            for (int mm = 0; mm < 4; mm++)
#pragma unroll
                for (int c = 0; c < 4; c++) acc[mm][c] = 0ull;
#pragma unroll
            for (int mm = 0; mm < 4; mm++) {
                if (mm >= mcnt) break;
                ulonglong2 v = *(const ulonglong2*)&S->srh[mbase + mm][cks * 4];
#pragma unroll
                for (int c = 0; c < 4; c++) {
                    acc[mm][c] = ffma2(wc2[0][c], v.x, acc[mm][c]);
                    acc[mm][c] = ffma2(wc2[1][c], v.y, acc[mm][c]);
                }
            }
#pragma unroll
            for (int mm = 0; mm < 4; mm++) {
                if (mm >= mcnt) break;
                float4 s;
                s.x = hadd2(acc[mm][0]); s.y = hadd2(acc[mm][1]);
                s.z = hadd2(acc[mm][2]); s.w = hadd2(acc[mm][3]);
                *reinterpret_cast<float4*>(
                    &S->ps[(cks * M_ + mbase + mm) * 64 + cng * 4]) = s;
            }
        }
        __syncthreads();

        // ---- Phase D: cand finalize + h update + output
        if (tid < M_ * 32) {
            int m = tid >> 5, n0 = (tid & 31) * 2;
            ull s = *(const ull*)&S->sy2[buf][m][n0];
#pragma unroll
            for (int k2 = 0; k2 < 16; k2++)
                s = add2(s, *(const ull*)&S->ps[(k2 * M_ + m) * 64 + n0]);
            float c0, c1; unpack2(s, c0, c1);
            c0 = tanh_f(c0); c1 = tanh_f(c1);
            float2 uv = *(const float2*)&S->su[m][n0];
            float2 hv = *(const float2*)&S->sh[m][n0];
            float a   = S->sa[buf][m];
            float uh0 = (1.0f - a) * uv.x;
            float uh1 = (1.0f - a) * uv.y;
            float hn0 = uh0 * hv.x + (1.0f - uh0) * c0;
            float hn1 = uh1 * hv.y + (1.0f - uh1) * c1;
            bool valid = (t < S->sl[m]);
            float2 nh; nh.x = valid ? hn0 : hv.x; nh.y = valid ? hn1 : hv.y;
            *(float2*)&S->sh[m][n0] = nh;
            int b = b0 + m;
            if (b < B_) {
                float2 o; o.x = valid ? hn0 : 0.0f; o.y = valid ? hn1 : 0.0f;
                *(float2*)&out[(b * T_ + t) * 64 + n0] = o;
            }
        }
        asm volatile("cp.async.wait_group 0;");
        __syncthreads();
    }
}

extern "C" void kernel_launch(void* const* d_in, const int* in_sizes, int n_in,
                              void* d_out, int out_size) {
    const float* x   = (const float*)d_in[0];
    const int*   sl  = (const int*)  d_in[1];
    const float* att = (const float*)d_in[2];
    const float* gk  = (const float*)d_in[3];
    const float* gb  = (const float*)d_in[4];
    const float* ck  = (const float*)d_in[5];
    const float* cb  = (const float*)d_in[6];
    float* out = (float*)d_out;

    pre_kernel<<<PRE_GRID, PRE_THREADS>>>(x, gk, gb, ck, cb);

    cudaFuncSetAttribute(augru_rec,
                         cudaFuncAttributeMaxDynamicSharedMemorySize, RSMEM_BYTES);
    augru_rec<<<NCTA_R, RTHREADS, RSMEM_BYTES>>>(sl, att, gk, ck, out);
}

// round 5
// speedup vs baseline: 1.7877x; 1.3156x over previous
#include <cuda_runtime.h>
#include <cstdint>

// AUGRU, B=2048, T=200, D=H=64.
//  K1 (pre): Y1 = x@Wgx + gb [BT,128], Y2 = x@Wcx + cb [BT,64]
//            register-blocked SGEMM, W in SMEM, f32x2 col-pair accumulators.
//  K2 (rec): persistent recurrence, K=64 h-part, NT=2 mappings (halved
//            partial-reduction smem traffic), f32x2 everywhere.

#define B_ 2048
#define T_ 200
#define D_ 64
#define H_ 64

typedef unsigned long long ull;

__device__ float Y1g[B_ * T_ * 128];
__device__ float Y2g[B_ * T_ * 64];

__device__ __forceinline__ ull pack2(float lo, float hi) {
    ull r; asm("mov.b64 %0, {%1, %2};" : "=l"(r) : "f"(lo), "f"(hi)); return r;
}
__device__ __forceinline__ void unpack2(ull v, float& lo, float& hi) {
    asm("mov.b64 {%0, %1}, %2;" : "=f"(lo), "=f"(hi) : "l"(v));
}
__device__ __forceinline__ ull ffma2(ull a, ull b, ull c) {
    ull d; asm("fma.rn.f32x2 %0, %1, %2, %3;" : "=l"(d) : "l"(a), "l"(b), "l"(c)); return d;
}
__device__ __forceinline__ ull add2(ull a, ull b) {
    ull d; asm("add.rn.f32x2 %0, %1, %2;" : "=l"(d) : "l"(a), "l"(b)); return d;
}
__device__ __forceinline__ float hadd2(ull v) {
    float lo, hi; unpack2(v, lo, hi); return lo + hi;
}
__device__ __forceinline__ float sigmoid_f(float x) {
    return __fdividef(1.0f, 1.0f + __expf(-x));
}
__device__ __forceinline__ float tanh_f(float x) {
    float e = __expf(2.0f * x);
    return 1.0f - __fdividef(2.0f, e + 1.0f);
}
__device__ __forceinline__ void cpa16(void* s, const void* g) {
    uint32_t sa = (uint32_t)__cvta_generic_to_shared(s);
    asm volatile("cp.async.ca.shared.global [%0], [%1], 16;" :: "r"(sa), "l"(g));
}
__device__ __forceinline__ void cpa4(void* s, const void* g) {
    uint32_t sa = (uint32_t)__cvta_generic_to_shared(s);
    asm volatile("cp.async.ca.shared.global [%0], [%1], 4;" :: "r"(sa), "l"(g));
}

// ============================ K1: precompute ================================
#define PT 256
#define PGRID 296
#define NTILES ((B_ * T_) / 64)   // 6400

struct PSmem {
    float w[64][192];       // combined [Wgx | Wcx], k-major
    float sx[2][64][64];    // x tile double buffer
};
#define PSMEM_BYTES ((int)sizeof(PSmem))

__global__ __launch_bounds__(PT, 2)
void pre_kernel(const float* __restrict__ x,   // [B*T, 64]
                const float* __restrict__ gk,  // [128,128]
                const float* __restrict__ gb,
                const float* __restrict__ ck,  // [128,64]
                const float* __restrict__ cb)
{
    extern __shared__ char praw[];
    PSmem* S = reinterpret_cast<PSmem*>(praw);
    const int tid = threadIdx.x;
    const int cg  = tid & 31;   // col-pair group: cols {2cg, 2cg+1} + 64j
    const int rg  = tid >> 5;   // row group: rows rg*8 .. rg*8+7

    // Load combined W (x-half rows k=0..63) into smem
    for (int idx = tid; idx < 64 * 48; idx += PT) {
        int k = idx / 48, c4 = idx % 48;
        float4 v;
        if (c4 < 32) v = ((const float4*)(gk + k * 128))[c4];
        else         v = ((const float4*)(ck + k * 64))[c4 - 32];
        ((float4*)&S->w[k][0])[c4] = v;
    }
    // Packed biases for this thread's 3 col-pairs
    ull bias[3];
#pragma unroll
    for (int j = 0; j < 3; j++) {
        int c = 64 * j + 2 * cg;
        float lo = (c < 128) ? gb[c] : cb[c - 128];
        float hi = (c < 128) ? gb[c + 1] : cb[c + 1 - 128];
        bias[j] = pack2(lo, hi);
    }

    int tile = blockIdx.x;
    auto prefetch = [&](int tl, int bb) {
        const char* src = (const char*)(x + (size_t)tl * 64 * 64);
        char* dst = (char*)&S->sx[bb][0][0];
#pragma unroll
        for (int i = 0; i < 4; i++)
            cpa16(dst + tid * 16 + i * 4096, src + tid * 16 + i * 4096);
        asm volatile("cp.async.commit_group;");
    };
    prefetch(tile, 0);
    int buf = 0;

    for (; tile < NTILES; tile += PGRID) {
        int nt = tile + PGRID;
        if (nt < NTILES) prefetch(nt, buf ^ 1);
        else asm volatile("cp.async.commit_group;");
        asm volatile("cp.async.wait_group 1;");
        __syncthreads();   // tile data (and W on first iter) visible

        ull acc[8][3];
#pragma unroll
        for (int r = 0; r < 8; r++)
#pragma unroll
            for (int j = 0; j < 3; j++) acc[r][j] = bias[j];

        const float* xs = &S->sx[buf][rg * 8][0];
#pragma unroll 4
        for (int kk = 0; kk < 16; kk++) {
            ull bx[4][3];
#pragma unroll
            for (int ks = 0; ks < 4; ks++)
#pragma unroll
                for (int j = 0; j < 3; j++)
                    bx[ks][j] = *(const ull*)&S->w[kk * 4 + ks][64 * j + 2 * cg];
#pragma unroll
            for (int r = 0; r < 8; r++) {
                float4 a = *(const float4*)(xs + r * 64 + kk * 4);
                ull a0 = pack2(a.x, a.x), a1 = pack2(a.y, a.y);
                ull a2 = pack2(a.z, a.z), a3 = pack2(a.w, a.w);
#pragma unroll
                for (int j = 0; j < 3; j++) {
                    acc[r][j] = ffma2(bx[0][j], a0, acc[r][j]);
                    acc[r][j] = ffma2(bx[1][j], a1, acc[r][j]);
                    acc[r][j] = ffma2(bx[2][j], a2, acc[r][j]);
                    acc[r][j] = ffma2(bx[3][j], a3, acc[r][j]);
                }
            }
        }

#pragma unroll
        for (int r = 0; r < 8; r++) {
            int row = tile * 64 + rg * 8 + r;
            float lo, hi;
            unpack2(acc[r][0], lo, hi);
            *(float2*)&Y1g[row * 128 + 2 * cg]      = make_float2(lo, hi);
            unpack2(acc[r][1], lo, hi);
            *(float2*)&Y1g[row * 128 + 64 + 2 * cg] = make_float2(lo, hi);
            unpack2(acc[r][2], lo, hi);
            *(float2*)&Y2g[row * 64 + 2 * cg]       = make_float2(lo, hi);
        }
        __syncthreads();   // all reads of sx[buf] done before it is refilled
        buf ^= 1;
    }
}

// ============================ K2: recurrence ================================
#define M_ 7
#define RTHREADS 256
#define NCTA_R ((B_ + M_ - 1) / M_)   // 293

struct RSmem {
    float sy1[2][M_][128];
    float sy2[2][M_][64];
    float sh[M_][64];
    float srh[M_][64];
    float su[M_][64];
    float ps[3584];          // gate [4][7][128] / cand [8][7][64]
    float sa[2][8];
    int   sl[8];
};
#define RSMEM_BYTES ((int)sizeof(RSmem))

__global__ __launch_bounds__(RTHREADS, 2)
void augru_rec(const int*   __restrict__ slen_g,
               const float* __restrict__ att,   // [B,T]
               const float* __restrict__ gk,
               const float* __restrict__ ck,
               float*       __restrict__ out)
{
    extern __shared__ char smem_raw[];
    RSmem* S = reinterpret_cast<RSmem*>(smem_raw);

    const int tid = threadIdx.x;
    const int b0  = blockIdx.x * M_;

    // gate: 64 col-pairs (NT=2) x 4 k-slices (16 k = 8 kp)
    const int gng = tid & 63;
    const int gks = tid >> 6;
    // cand: 32 col-pairs (NT=2) x 8 k-slices (8 k = 4 kp)
    const int cng = tid & 31;
    const int cks = tid >> 5;

    ull wg2[8][2];
#pragma unroll
    for (int kp = 0; kp < 8; kp++) {
        int k = 64 + gks * 16 + 2 * kp;
#pragma unroll
        for (int c = 0; c < 2; c++)
            wg2[kp][c] = pack2(gk[k * 128 + 2 * gng + c],
                               gk[(k + 1) * 128 + 2 * gng + c]);
    }
    ull wc2[4][2];
#pragma unroll
    for (int kp = 0; kp < 4; kp++) {
        int k = 64 + cks * 8 + 2 * kp;
#pragma unroll
        for (int c = 0; c < 2; c++)
            wc2[kp][c] = pack2(ck[k * 64 + 2 * cng + c],
                               ck[(k + 1) * 64 + 2 * cng + c]);
    }

    for (int idx = tid; idx < M_ * 64; idx += RTHREADS)
        (&S->sh[0][0])[idx] = 0.0f;
    if (tid < M_) {
        int b = b0 + tid; if (b >= B_) b = B_ - 1;
        S->sl[tid] = slen_g[b];
    }

    const int y1m = tid >> 5, y1q = tid & 31;
    const int y2m = tid >> 4, y2q = tid & 15;
    int by1 = b0 + y1m; if (by1 >= B_) by1 = B_ - 1;
    int by2 = b0 + y2m; if (by2 >= B_) by2 = B_ - 1;
    int ba  = b0 + tid; if (ba  >= B_) ba  = B_ - 1;

    auto do_prefetch = [&](int tt, int bb) {
        if (tid < 224)
            cpa16((char*)&S->sy1[bb][0][0] + tid * 16,
                  &Y1g[(by1 * T_ + tt) * 128 + y1q * 4]);
        if (tid < 112)
            cpa16((char*)&S->sy2[bb][0][0] + tid * 16,
                  &Y2g[(by2 * T_ + tt) * 64 + y2q * 4]);
        if (tid < M_)
            cpa4(&S->sa[bb][tid], &att[ba * T_ + tt]);
        asm volatile("cp.async.commit_group;");
    };

    do_prefetch(0, 0);
    asm volatile("cp.async.wait_group 0;");
    __syncthreads();

    for (int t = 0; t < T_; ++t) {
        const int buf  = t & 1;
        const int nbuf = buf ^ 1;
        do_prefetch((t + 1 < T_) ? t + 1 : t, nbuf);

        // ---- Phase A: gate h-GEMM partials (k-pair FFMA2, 2 cols)
#pragma unroll
        for (int mh = 0; mh < 2; mh++) {
            const int mbase = mh * 4;
            const int mcnt  = mh ? 3 : 4;
            ull acc[4][2];
#pragma unroll
            for (int mm = 0; mm < 4; mm++)
                { acc[mm][0] = 0ull; acc[mm][1] = 0ull; }
#pragma unroll
            for (int mm = 0; mm < 4; mm++) {
                if (mm >= mcnt) break;
                const ulonglong2* p =
                    (const ulonglong2*)&S->sh[mbase + mm][gks * 16];
                ulonglong2 v0 = p[0], v1 = p[1], v2 = p[2], v3 = p[3];
#pragma unroll
                for (int c = 0; c < 2; c++) {
                    acc[mm][c] = ffma2(wg2[0][c], v0.x, acc[mm][c]);
                    acc[mm][c] = ffma2(wg2[1][c], v0.y, acc[mm][c]);
                    acc[mm][c] = ffma2(wg2[2][c], v1.x, acc[mm][c]);
                    acc[mm][c] = ffma2(wg2[3][c], v1.y, acc[mm][c]);
                    acc[mm][c] = ffma2(wg2[4][c], v2.x, acc[mm][c]);
                    acc[mm][c] = ffma2(wg2[5][c], v2.y, acc[mm][c]);
                    acc[mm][c] = ffma2(wg2[6][c], v3.x, acc[mm][c]);
                    acc[mm][c] = ffma2(wg2[7][c], v3.y, acc[mm][c]);
                }
            }
#pragma unroll
            for (int mm = 0; mm < 4; mm++) {
                if (mm >= mcnt) break;
                *(float2*)&S->ps[(gks * M_ + mbase + mm) * 128 + 2 * gng] =
                    make_float2(hadd2(acc[mm][0]), hadd2(acc[mm][1]));
            }
        }
        __syncthreads();

        // ---- Phase B: gate finalize (4 packed adds, sigmoid -> srh/su)
#pragma unroll
        for (int it = 0; it < 2; it++) {
            int p = tid + it * 256;
            if (p < M_ * 64) {
                int m = p >> 6, n0 = (p & 63) * 2;
                ull s = *(const ull*)&S->sy1[buf][m][n0];
#pragma unroll
                for (int k2 = 0; k2 < 4; k2++)
                    s = add2(s, *(const ull*)&S->ps[(k2 * M_ + m) * 128 + n0]);
                float g0, g1; unpack2(s, g0, g1);
                g0 = sigmoid_f(g0); g1 = sigmoid_f(g1);
                if (n0 < 64) {
                    float2 hv = *(const float2*)&S->sh[m][n0];
                    *(float2*)&S->srh[m][n0] = make_float2(g0 * hv.x, g1 * hv.y);
                } else {
                    *(float2*)&S->su[m][n0 - 64] = make_float2(g0, g1);
                }
            }
        }
        __syncthreads();

        // ---- Phase C: cand rh-GEMM partials
#pragma unroll
        for (int mh = 0; mh < 2; mh++) {
            const int mbase = mh * 4;
            const int mcnt  = mh ? 3 : 4;
            ull acc[4][2];
#pragma unroll
            for (int mm = 0; mm < 4; mm++)
                { acc[mm][0] = 0ull; acc[mm][1] = 0ull; }
#pragma unroll
            for (int mm = 0; mm < 4; mm++) {
                if (mm >= mcnt) break;
                const ulonglong2* p =
                    (const ulonglong2*)&S->srh[mbase + mm][cks * 8];
                ulonglong2 v0 = p[0], v1 = p[1];
#pragma unroll
                for (int c = 0; c < 2; c++) {
                    acc[mm][c] = ffma2(wc2[0][c], v0.x, acc[mm][c]);
                    acc[mm][c] = ffma2(wc2[1][c], v0.y, acc[mm][c]);
                    acc[mm][c] = ffma2(wc2[2][c], v1.x, acc[mm][c]);
                    acc[mm][c] = ffma2(wc2[3][c], v1.y, acc[mm][c]);
                }
            }
#pragma unroll
            for (int mm = 0; mm < 4; mm++) {
                if (mm >= mcnt) break;
                *(float2*)&S->ps[(cks * M_ + mbase + mm) * 64 + 2 * cng] =
                    make_float2(hadd2(acc[mm][0]), hadd2(acc[mm][1]));
            }
        }
        __syncthreads();

        // ---- Phase D: cand finalize + h update + output
        if (tid < M_ * 32) {
            int m = tid >> 5, n0 = (tid & 31) * 2;
            ull s = *(const ull*)&S->sy2[buf][m][n0];
#pragma unroll
            for (int k2 = 0; k2 < 8; k2++)
                s = add2(s, *(const ull*)&S->ps[(k2 * M_ + m) * 64 + n0]);
            float c0, c1; unpack2(s, c0, c1);
            c0 = tanh_f(c0); c1 = tanh_f(c1);
            float2 uv = *(const float2*)&S->su[m][n0];
            float2 hv = *(const float2*)&S->sh[m][n0];
            float a   = S->sa[buf][m];
            float uh0 = (1.0f - a) * uv.x;
            float uh1 = (1.0f - a) * uv.y;
            float hn0 = uh0 * hv.x + (1.0f - uh0) * c0;
            float hn1 = uh1 * hv.y + (1.0f - uh1) * c1;
            bool valid = (t < S->sl[m]);
            *(float2*)&S->sh[m][n0] =
                make_float2(valid ? hn0 : hv.x, valid ? hn1 : hv.y);
            int b = b0 + m;
            if (b < B_)
                *(float2*)&out[(b * T_ + t) * 64 + n0] =
                    make_float2(valid ? hn0 : 0.0f, valid ? hn1 : 0.0f);
        }
        asm volatile("cp.async.wait_group 0;");
        __syncthreads();
    }
}

extern "C" void kernel_launch(void* const* d_in, const int* in_sizes, int n_in,
                              void* d_out, int out_size) {
    const float* x   = (const float*)d_in[0];
    const int*   sl  = (const int*)  d_in[1];
    const float* att = (const float*)d_in[2];
    const float* gk  = (const float*)d_in[3];
    const float* gb  = (const float*)d_in[4];
    const float* ck  = (const float*)d_in[5];
    const float* cb  = (const float*)d_in[6];
    float* out = (float*)d_out;

    cudaFuncSetAttribute(pre_kernel,
                         cudaFuncAttributeMaxDynamicSharedMemorySize, PSMEM_BYTES);
    pre_kernel<<<PGRID, PT, PSMEM_BYTES>>>(x, gk, gb, ck, cb);

    cudaFuncSetAttribute(augru_rec,
                         cudaFuncAttributeMaxDynamicSharedMemorySize, RSMEM_BYTES);
    augru_rec<<<NCTA_R, RTHREADS, RSMEM_BYTES>>>(sl, att, gk, ck, out);
}